// round 2
// baseline (speedup 1.0000x reference)
#include <cuda_runtime.h>
#include <math.h>

#define Hdim 1024
#define INdim 512
#define Bdim 256
#define Tdim 256
#define HB (Hdim * Bdim)

#define DTc 0.1f
#define DELTA_T 1.0f
#define Z_MIN_C 0.001f
#define Z_MAX_C 0.1f

// ---------------- device scratch (no cudaMalloc allowed) ----------------
// g_Az / g_Ar: precomputed input projections, [T][H][B]. 256 MiB each.
// g_Az[t] is re-used to stage v_t (h,b-major) for the final transpose.
__device__ __align__(128) float g_Az[(size_t)Tdim * HB];
__device__ __align__(128) float g_Ar[(size_t)Tdim * HB];
__device__ __align__(128) float g_X[HB];
__device__ __align__(128) float g_U[HB];
__device__ __align__(128) float g_v[HB];
__device__ __align__(128) float g_r[HB];
__device__ __align__(128) float g_m[HB];
__device__ __align__(128) float g_G1[HB];
__device__ __align__(128) float g_G2[HB];

__device__ __forceinline__ float sigm(float x) {
    return 1.0f / (1.0f + expf(-x));
}

// ---------------- init state ----------------
__global__ void init_state_kernel() {
    int i = blockIdx.x * blockDim.x + threadIdx.x;
    if (i < HB) {
        g_X[i] = 1.0f;
        g_U[i] = 0.9f;
        g_v[i] = 0.0f;
    }
}

// ---------------- precompute GEMM: C[t] = W @ x_t + bias -----------------
// W: (1024 x 512) row-major.  x_t: (512 x 256) row-major.  C: [T][1024][256].
// Tile 128x128x8, 256 threads, 8x8 microtile.
template <int WHICH>  // 0 -> g_Az, 1 -> g_Ar
__global__ __launch_bounds__(256) void pre_gemm(
    const float* __restrict__ W, const float* __restrict__ x,
    const float* __restrict__ bias)
{
    const int t = blockIdx.z;
    const float* Bp = x + (size_t)t * (INdim * Bdim);
    float* C = (WHICH == 0 ? g_Az : g_Ar) + (size_t)t * HB;

    __shared__ float As[8][128];
    __shared__ float Bs[8][128];

    const int tid = threadIdx.x;
    const int tx = tid % 16;          // 0..15 -> 8 output cols each
    const int ty = tid / 16;          // 0..15 -> 8 output rows each
    const int m0 = blockIdx.y * 128;
    const int n0 = blockIdx.x * 128;

    const int arow = tid / 2;         // 0..127
    const int acol = (tid % 2) * 4;   // 0 or 4
    const int brow = tid / 32;        // 0..7
    const int bcol = (tid % 32) * 4;  // 0..124

    float acc[8][8];
#pragma unroll
    for (int i = 0; i < 8; ++i)
#pragma unroll
        for (int j = 0; j < 8; ++j) acc[i][j] = 0.0f;

    for (int k0 = 0; k0 < INdim; k0 += 8) {
        float4 a4 = *(const float4*)&W[(size_t)(m0 + arow) * INdim + k0 + acol];
        As[acol + 0][arow] = a4.x;
        As[acol + 1][arow] = a4.y;
        As[acol + 2][arow] = a4.z;
        As[acol + 3][arow] = a4.w;
        *(float4*)&Bs[brow][bcol] =
            *(const float4*)&Bp[(size_t)(k0 + brow) * Bdim + n0 + bcol];
        __syncthreads();
#pragma unroll
        for (int k = 0; k < 8; ++k) {
            float a[8], b[8];
            *(float4*)&a[0] = *(const float4*)&As[k][ty * 8];
            *(float4*)&a[4] = *(const float4*)&As[k][ty * 8 + 4];
            *(float4*)&b[0] = *(const float4*)&Bs[k][tx * 8];
            *(float4*)&b[4] = *(const float4*)&Bs[k][tx * 8 + 4];
#pragma unroll
            for (int i = 0; i < 8; ++i)
#pragma unroll
                for (int j = 0; j < 8; ++j) acc[i][j] += a[i] * b[j];
        }
        __syncthreads();
    }

#pragma unroll
    for (int i = 0; i < 8; ++i) {
        float bv = bias[m0 + ty * 8 + i];
        float4 o0 = make_float4(acc[i][0] + bv, acc[i][1] + bv,
                                acc[i][2] + bv, acc[i][3] + bv);
        float4 o1 = make_float4(acc[i][4] + bv, acc[i][5] + bv,
                                acc[i][6] + bv, acc[i][7] + bv);
        float* crow = &C[(size_t)(m0 + ty * 8 + i) * Bdim + n0 + tx * 8];
        *(float4*)&crow[0] = o0;
        *(float4*)&crow[4] = o1;
    }
}

// ---------------- elementwise step kernel ----------------
// Fuses epilogue of step t-1 (z_t gate + v update + output staging) with the
// state prep of step t (r, X, U, m). Grid: 1024 blocks x 256 threads; h = blk.
__global__ __launch_bounds__(256) void step_elem(
    const float* __restrict__ c_x, const float* __restrict__ c_u,
    const float* __restrict__ c_U, int t)
{
    const int idx = blockIdx.x * 256 + threadIdx.x;
    const int h = idx >> 8;  // B == 256

    float v = g_v[idx];
    if (t > 0) {
        const size_t off = (size_t)(t - 1) * HB + idx;
        float z = DTc * sigm(g_G1[idx] + g_Az[off]);
        v = (1.0f - z) * v + DTc * (g_G2[idx] + g_Ar[off]);
        g_v[idx] = v;
        g_Az[off] = v;  // stage v_{t-1} for final transpose
    }
    if (t < Tdim) {
        const float r = sigm(v);
        const float zx = Z_MIN_C + (Z_MAX_C - Z_MIN_C) * sigm(c_x[h]);
        const float zu = Z_MIN_C + (Z_MAX_C - Z_MIN_C) * sigm(c_u[h]);
        const float Uc = 0.9f * sigm(c_U[h]);
        const float X = g_X[idx];
        const float U = g_U[idx];
        float Xn = zx + (1.0f - zx) * X - DELTA_T * U * X * r;
        float Un = Uc * zu + (1.0f - zu) * U + DELTA_T * Uc * (1.0f - U) * r;
        Un = fminf(fmaxf(Un, Uc), 1.0f);
        g_X[idx] = Xn;
        g_U[idx] = Un;
        g_r[idx] = r;
        g_m[idx] = Un * Xn * r;
    }
}

// ---------------- recurrent dual GEMM: G1 = K@r, G2 = w_r@m ----------------
// M=1024, N=256, K=1024 each. Tile 64x64x16, 256 threads, 4x4 microtile.
// Grid: (4, 16, 2) = 128 blocks (one wave, ~1 block/SM).
__global__ __launch_bounds__(256) void step_gemm(
    const float* __restrict__ Kmat, const float* __restrict__ Wr)
{
    const float* A = blockIdx.z ? Wr : Kmat;
    const float* Bp = blockIdx.z ? g_m : g_r;
    float* C = blockIdx.z ? g_G2 : g_G1;

    __shared__ float As[16][64];
    __shared__ float Bs[16][64];

    const int tid = threadIdx.x;
    const int tx = tid % 16;
    const int ty = tid / 16;
    const int m0 = blockIdx.y * 64;
    const int n0 = blockIdx.x * 64;

    const int arow = tid / 4;         // 0..63
    const int acol = (tid % 4) * 4;   // 0,4,8,12
    const int brow = tid / 16;        // 0..15
    const int bcol = (tid % 16) * 4;  // 0..60

    float acc[4][4];
#pragma unroll
    for (int i = 0; i < 4; ++i)
#pragma unroll
        for (int j = 0; j < 4; ++j) acc[i][j] = 0.0f;

    for (int k0 = 0; k0 < Hdim; k0 += 16) {
        float4 a4 = *(const float4*)&A[(size_t)(m0 + arow) * Hdim + k0 + acol];
        As[acol + 0][arow] = a4.x;
        As[acol + 1][arow] = a4.y;
        As[acol + 2][arow] = a4.z;
        As[acol + 3][arow] = a4.w;
        *(float4*)&Bs[brow][bcol] =
            *(const float4*)&Bp[(size_t)(k0 + brow) * Bdim + n0 + bcol];
        __syncthreads();
#pragma unroll
        for (int k = 0; k < 16; ++k) {
            float a[4], b[4];
            *(float4*)&a[0] = *(const float4*)&As[k][ty * 4];
            *(float4*)&b[0] = *(const float4*)&Bs[k][tx * 4];
#pragma unroll
            for (int i = 0; i < 4; ++i)
#pragma unroll
                for (int j = 0; j < 4; ++j) acc[i][j] += a[i] * b[j];
        }
        __syncthreads();
    }

#pragma unroll
    for (int i = 0; i < 4; ++i) {
        float4 o = make_float4(acc[i][0], acc[i][1], acc[i][2], acc[i][3]);
        *(float4*)&C[(size_t)(m0 + ty * 4 + i) * Bdim + n0 + tx * 4] = o;
    }
}

// ---------------- final transpose: g_Az[t][h][b] -> out[t][b][h] ----------
__global__ __launch_bounds__(256) void transpose_out(float* __restrict__ out)
{
    __shared__ float tile[32][33];
    const int t = blockIdx.z;
    const int h0 = blockIdx.y * 32;
    const int b0 = blockIdx.x * 32;
    const float* src = g_Az + (size_t)t * HB;
    float* dst = out + (size_t)t * HB;
    const int lx = threadIdx.x;  // 0..31
    const int ly = threadIdx.y;  // 0..7

#pragma unroll
    for (int i = 0; i < 32; i += 8)
        tile[ly + i][lx] = src[(size_t)(h0 + ly + i) * Bdim + b0 + lx];
    __syncthreads();
#pragma unroll
    for (int i = 0; i < 32; i += 8)
        dst[(size_t)(b0 + ly + i) * Hdim + h0 + lx] = tile[lx][ly + i];
}

// ---------------- launch ----------------
extern "C" void kernel_launch(void* const* d_in, const int* in_sizes, int n_in,
                              void* d_out, int out_size)
{
    const float* x   = (const float*)d_in[0];  // (T, IN, B)
    const float* c_x = (const float*)d_in[1];  // (H,1)
    const float* c_u = (const float*)d_in[2];  // (H,1)
    const float* c_U = (const float*)d_in[3];  // (H,1)
    const float* w_r = (const float*)d_in[4];  // (H,H)
    const float* p_r = (const float*)d_in[5];  // (H,IN)
    const float* b_r = (const float*)d_in[6];  // (H,1)
    const float* g_z = (const float*)d_in[7];  // (H,1)
    const float* Km  = (const float*)d_in[8];  // (H,H)
    const float* p_z = (const float*)d_in[9];  // (H,IN)
    float* out = (float*)d_out;                // (T, B, H)

    init_state_kernel<<<HB / 256, 256>>>();

    dim3 pgrid(Bdim / 128, Hdim / 128, Tdim);  // (2, 8, 256)
    pre_gemm<0><<<pgrid, 256>>>(p_z, x, g_z);
    pre_gemm<1><<<pgrid, 256>>>(p_r, x, b_r);

    dim3 sgrid(Bdim / 64, Hdim / 64, 2);       // (4, 16, 2) = 128 blocks
    for (int t = 0; t < Tdim; ++t) {
        step_elem<<<Hdim, 256>>>(c_x, c_u, c_U, t);
        step_gemm<<<sgrid, 256>>>(Km, w_r);
    }
    step_elem<<<Hdim, 256>>>(c_x, c_u, c_U, Tdim);  // final epilogue only

    dim3 tgrid(Bdim / 32, Hdim / 32, Tdim);    // (8, 32, 256)
    transpose_out<<<tgrid, dim3(32, 8)>>>(out);
}